// round 1
// baseline (speedup 1.0000x reference)
#include <cuda_runtime.h>
#include <math.h>

#define NB    64
#define DIM   8
#define NPTS  2097152
#define BETA_F 1e-6f
// log(float(1e-6)) in f32
#define LOG_BETA (-13.815511f)

// Scratch tables built by setup kernel each launch (deterministic).
__device__ float  g_mesh[NB + 2];           // [65] + inf guard slot
__device__ float4 g_tab [NB * DIM];         // per (bin,dim): {v1, slope=(v2-v1)/h, F_pre, mesh_k}

// ---------------------------------------------------------------------------
// Setup: build mesh / elmt / normalized pdf / cumulative F, pack tables.
// One block, trivial cost. Mesh in double (pow chain), rest f32 (tol 1e-3).
// ---------------------------------------------------------------------------
__global__ void setup_kernel(const float* __restrict__ p)
{
    __shared__ float s_mesh[NB + 1];
    __shared__ float s_elmt[NB];
    __shared__ float s_ep[(NB - 1) * DIM];
    __shared__ float s_pdf[(NB + 1) * DIM];
    __shared__ float s_F[NB * DIM];

    const int t = threadIdx.x;

    if (t <= NB) {
        double idx = (double)t - 32.0;
        double x1L = 10.0 * (1.2 - 1.0) / (pow(1.2, 32.0) - 1.0);
        double xr  = (pow(1.2, fabs(idx)) - 1.0) / (1.2 - 1.0);
        xr = (idx >= 0.0) ? x1L * xr : -x1L * xr;
        xr = (xr + 10.0) / 20.0;
        float mv = (float)xr;
        if (t == 0)  mv = 0.0f;
        if (t == NB) mv = 1.0f;
        s_mesh[t] = mv;
    }
    __syncthreads();
    if (t < NB) s_elmt[t] = s_mesh[t + 1] - s_mesh[t];
    for (int i = t; i < (NB - 1) * DIM; i += blockDim.x)
        s_ep[i] = expf(p[i]);
    __syncthreads();

    if (t < DIM) {
        // normalize pdf for dim t
        float sum = 0.0f;
        for (int i = 0; i < NB - 1; i++)
            sum += s_ep[i * DIM + t] * 0.5f * (s_elmt[i] + s_elmt[i + 1]);
        float scale = (1.0f - (s_elmt[0] + s_elmt[NB - 1]) * BETA_F * 0.5f) / sum;

        s_pdf[t] = BETA_F;
        s_pdf[NB * DIM + t] = BETA_F;
        for (int i = 0; i < NB - 1; i++)
            s_pdf[(i + 1) * DIM + t] = scale * s_ep[i * DIM + t];

        // cumulative bin integrals
        s_F[t] = 0.0f;
        float cum = 0.0f;
        for (int i = 0; i < NB - 1; i++) {
            cum += 0.5f * (s_pdf[i * DIM + t] + s_pdf[(i + 1) * DIM + t]) * s_elmt[i];
            s_F[(i + 1) * DIM + t] = cum;
        }
    }
    __syncthreads();

    if (t <= NB) g_mesh[t] = s_mesh[t];
    if (t == 0)  g_mesh[NB + 1] = INFINITY;   // binary-search guard

    for (int i = t; i < NB * DIM; i += blockDim.x) {
        int k = i / DIM, d = i % DIM;
        float v1 = s_pdf[k * DIM + d];
        float v2 = s_pdf[(k + 1) * DIM + d];
        float h  = s_elmt[k];
        g_tab[i] = make_float4(v1, (v2 - v1) / h, s_F[i], s_mesh[k]);
    }
}

// ---------------------------------------------------------------------------
// Main: one point per thread. Tables staged in shared (8.3 KB).
// ---------------------------------------------------------------------------
__global__ void __launch_bounds__(256)
cdf_kernel(const float*  __restrict__ x,
           const float*  __restrict__ logdet_in,
           float*        __restrict__ y_out,
           float*        __restrict__ ld_out)
{
    __shared__ float  s_mesh[NB + 2];
    __shared__ float4 s_tab[NB * DIM];

    const int t = threadIdx.x;
    if (t < NB + 2) s_mesh[t] = g_mesh[t];
    for (int i = t; i < NB * DIM; i += 256) s_tab[i] = g_tab[i];
    __syncthreads();

    const int i = blockIdx.x * 256 + t;
    if (i >= NPTS) return;

    const float4* xv = (const float4*)(x + (size_t)i * DIM);
    float4 a = xv[0], b = xv[1];
    float xr[DIM] = {a.x, a.y, a.z, a.w, b.x, b.y, b.z, b.w};
    float yv[DIM];
    float lsum = 0.0f;

#pragma unroll
    for (int d = 0; d < DIM; d++) {
        float xs = (xr[d] + 10.0f) * 0.05f;

        // searchsorted(mesh, xs, side='right') via 7-step branch-free search
        int lo = 0, hi = NB + 1;
#pragma unroll
        for (int s = 0; s < 7; s++) {
            int  mid = (lo + hi) >> 1;
            bool le  = (s_mesh[mid] <= xs);
            lo = le ? mid + 1 : lo;
            hi = le ? hi      : mid;
        }
        int  k     = lo - 1;
        bool cover = (k >= 0) && (k < NB);
        int  kc    = max(0, min(k, NB - 1));

        float4 tb = s_tab[kc * DIM + d];     // {v1, slope, F_pre, mesh_k}
        float  xm = xs - tb.w;

        float dld = fmaf(xm, tb.y, tb.x);                          // xm*slope + v1
        float yq  = fmaf(xm, fmaf(0.5f * xm, tb.y, tb.x), tb.z);   // F + xm*(v1 + xm*slope/2)
        if (!cover) { dld = 1.0f; yq = xs; }

        lsum += logf(dld);

        float yy = fmaf(yq, 20.0f, -10.0f);
        if (yy > 10.0f)  { lsum += LOG_BETA; yy = fmaf(BETA_F, yy - 10.0f,  10.0f); }
        if (yy < -10.0f) { lsum += LOG_BETA; yy = fmaf(BETA_F, yy + 10.0f, -10.0f); }
        yv[d] = yy;
    }

    float4* yo = (float4*)(y_out + (size_t)i * DIM);
    yo[0] = make_float4(yv[0], yv[1], yv[2], yv[3]);
    yo[1] = make_float4(yv[4], yv[5], yv[6], yv[7]);
    ld_out[i] = logdet_in[i] + lsum;
}

extern "C" void kernel_launch(void* const* d_in, const int* in_sizes, int n_in,
                              void* d_out, int out_size)
{
    const float* x      = (const float*)d_in[0];
    const float* logdet = (const float*)d_in[1];
    const float* p      = (const float*)d_in[2];
    float* out   = (float*)d_out;
    float* y_out = out;                      // [N*8]
    float* ld_out = out + (size_t)NPTS * DIM; // [N]

    setup_kernel<<<1, 256>>>(p);
    cdf_kernel<<<NPTS / 256, 256>>>(x, logdet, y_out, ld_out);
}

// round 2
// speedup vs baseline: 1.7177x; 1.7177x over previous
#include <cuda_runtime.h>
#include <math.h>

#define NB     64
#define DIM    8
#define NPTS   2097152
#define BETA_F 1e-6f
#define LOG_BETA (-13.815511f)

// Geometric-mesh constants: t = |x|*(R^32-1)/10 + 1, j = floor(log2(t)/log2(1.2))
#define GEO_C1   34.0821892f     // (1.2^32 - 1) / 10
#define GEO_INVL 3.80178402f     // 1 / log2(1.2)

// Tables rebuilt by setup kernel each launch (deterministic).
__device__ float2 g_mkpair[NB];         // {mesh[k], mesh[k+1]}
__device__ float  g_v1   [DIM * NB];    // [d*64+k] pdf[k,d]
__device__ float  g_slope[DIM * NB];    // (pdf[k+1,d]-pdf[k,d])/elmt[k]
__device__ float  g_F    [DIM * NB];    // F_ref[k,d]

// ---------------------------------------------------------------------------
// Setup: build mesh / normalized pdf / cumulative F, pack split tables.
// ---------------------------------------------------------------------------
__global__ void setup_kernel(const float* __restrict__ p)
{
    __shared__ float s_mesh[NB + 1];
    __shared__ float s_elmt[NB];
    __shared__ float s_ep[(NB - 1) * DIM];
    __shared__ float s_pdf[(NB + 1) * DIM];
    __shared__ float s_F[NB * DIM];

    const int t = threadIdx.x;

    if (t <= NB) {
        double idx = (double)t - 32.0;
        double x1L = 10.0 * (1.2 - 1.0) / (pow(1.2, 32.0) - 1.0);
        double xr  = (pow(1.2, fabs(idx)) - 1.0) / (1.2 - 1.0);
        xr = (idx >= 0.0) ? x1L * xr : -x1L * xr;
        xr = (xr + 10.0) / 20.0;
        float mv = (float)xr;
        if (t == 0)  mv = 0.0f;
        if (t == NB) mv = 1.0f;
        s_mesh[t] = mv;
    }
    __syncthreads();
    if (t < NB) s_elmt[t] = s_mesh[t + 1] - s_mesh[t];
    for (int i = t; i < (NB - 1) * DIM; i += blockDim.x)
        s_ep[i] = expf(p[i]);
    __syncthreads();

    if (t < DIM) {
        float sum = 0.0f;
        for (int i = 0; i < NB - 1; i++)
            sum += s_ep[i * DIM + t] * 0.5f * (s_elmt[i] + s_elmt[i + 1]);
        float scale = (1.0f - (s_elmt[0] + s_elmt[NB - 1]) * BETA_F * 0.5f) / sum;

        s_pdf[t] = BETA_F;
        s_pdf[NB * DIM + t] = BETA_F;
        for (int i = 0; i < NB - 1; i++)
            s_pdf[(i + 1) * DIM + t] = scale * s_ep[i * DIM + t];

        s_F[t] = 0.0f;
        float cum = 0.0f;
        for (int i = 0; i < NB - 1; i++) {
            cum += 0.5f * (s_pdf[i * DIM + t] + s_pdf[(i + 1) * DIM + t]) * s_elmt[i];
            s_F[(i + 1) * DIM + t] = cum;
        }
    }
    __syncthreads();

    if (t < NB) g_mkpair[t] = make_float2(s_mesh[t], s_mesh[t + 1]);

    for (int i = t; i < NB * DIM; i += blockDim.x) {
        int k = i / DIM, d = i % DIM;
        float v1 = s_pdf[k * DIM + d];
        float v2 = s_pdf[(k + 1) * DIM + d];
        float h  = s_elmt[k];
        g_v1   [d * NB + k] = v1;
        g_slope[d * NB + k] = (v2 - v1) / h;
        g_F    [d * NB + k] = s_F[k * DIM + d];
    }
}

// ---------------------------------------------------------------------------
// Main: one point per thread. Analytic geometric bin index + exact fixup.
// Split scalar tables -> bank = k % 32 (conflict-light).
// ---------------------------------------------------------------------------
__global__ void __launch_bounds__(256)
cdf_kernel(const float*  __restrict__ x,
           const float*  __restrict__ logdet_in,
           float*        __restrict__ y_out,
           float*        __restrict__ ld_out)
{
    __shared__ float2 s_mkpair[NB];
    __shared__ float  s_v1   [DIM * NB];
    __shared__ float  s_slope[DIM * NB];
    __shared__ float  s_F    [DIM * NB];

    const int t = threadIdx.x;
    if (t < NB) s_mkpair[t] = g_mkpair[t];
    for (int i = t; i < DIM * NB; i += 256) {
        s_v1[i]    = g_v1[i];
        s_slope[i] = g_slope[i];
        s_F[i]     = g_F[i];
    }
    __syncthreads();

    const int i = blockIdx.x * 256 + t;

    const float4* xv = (const float4*)(x + (size_t)i * DIM);
    float4 a4 = xv[0], b4 = xv[1];
    float xr[DIM] = {a4.x, a4.y, a4.z, a4.w, b4.x, b4.y, b4.z, b4.w};
    float yv[DIM];
    float lsum = 0.0f;

#pragma unroll
    for (int d = 0; d < DIM; d++) {
        float xi = xr[d];
        float xs = (xi + 10.0f) * 0.05f;
        bool cover = (xs >= 0.0f) && (xs < 1.0f);

        // Analytic candidate bin: geometric mesh inversion via one LG2
        float av = fabsf(xi);
        float tg = fmaf(av, GEO_C1, 1.0f);
        int   j  = (int)(__log2f(tg) * GEO_INVL);   // >= 0, trunc == floor
        j = min(j, 31);
        int k0 = (xi >= 0.0f) ? (32 + j) : (31 - j);
        k0 = min(max(k0, 0), NB - 1);

        // Exact fixup against true (f32) mesh values — matches searchsorted 'right'
        float2 mp = s_mkpair[k0];
        int k = k0;
        if (xs <  mp.x) k = k0 - 1;
        if (xs >= mp.y) k = k0 + 1;
        k = min(max(k, 0), NB - 1);
        float mk = (k == k0) ? mp.x : s_mkpair[k].x;   // rare divergent reload

        int   ti    = d * NB + k;
        float v1    = s_v1[ti];
        float slope = s_slope[ti];
        float Fp    = s_F[ti];

        float xm  = xs - mk;
        float dld = fmaf(xm, slope, v1);
        float yq  = fmaf(xm, fmaf(0.5f * xm, slope, v1), Fp);
        if (!cover) { yq = xs; dld = 1.0f; }

        lsum += __logf(dld);

        float yy = fmaf(yq, 20.0f, -10.0f);
        if (yy > 10.0f)  { lsum += LOG_BETA; yy = fmaf(BETA_F, yy - 10.0f,  10.0f); }
        if (yy < -10.0f) { lsum += LOG_BETA; yy = fmaf(BETA_F, yy + 10.0f, -10.0f); }
        yv[d] = yy;
    }

    float4* yo = (float4*)(y_out + (size_t)i * DIM);
    yo[0] = make_float4(yv[0], yv[1], yv[2], yv[3]);
    yo[1] = make_float4(yv[4], yv[5], yv[6], yv[7]);
    ld_out[i] = logdet_in[i] + lsum;
}

extern "C" void kernel_launch(void* const* d_in, const int* in_sizes, int n_in,
                              void* d_out, int out_size)
{
    const float* x      = (const float*)d_in[0];
    const float* logdet = (const float*)d_in[1];
    const float* p      = (const float*)d_in[2];
    float* out    = (float*)d_out;
    float* y_out  = out;                        // [N*8]
    float* ld_out = out + (size_t)NPTS * DIM;   // [N]

    setup_kernel<<<1, 256>>>(p);
    cdf_kernel<<<NPTS / 256, 256>>>(x, logdet, y_out, ld_out);
}

// round 3
// speedup vs baseline: 2.0337x; 1.1840x over previous
#include <cuda_runtime.h>
#include <math.h>

#define NB     64
#define DIM    8
#define NPTS   2097152
#define BETA_F 1e-6f
#define LOG_BETA (-13.815511f)

// Geometric-mesh inversion: t = |x|*(R^32-1)/10 + 1, j = floor(log2(t)/log2(1.2))
#define GEO_C1   34.0821892f     // (1.2^32 - 1) / 10
#define GEO_INVL 3.80178402f     // 1 / log2(1.2)

// Packed per-(dim,bin) table, rebuilt each launch: {v1, slope, F_pre, mesh_k}
__device__ float4 g_tab[DIM * NB];

// ---------------------------------------------------------------------------
// Setup: mesh via binary-expansion double powers (no pow()), normalize pdf,
// cumulative F, pack float4 table laid out [d][k].
// ---------------------------------------------------------------------------
__global__ void setup_kernel(const float* __restrict__ p)
{
    __shared__ float s_mesh[NB + 1];
    __shared__ float s_elmt[NB];
    __shared__ float s_ep[(NB - 1) * DIM];
    __shared__ float s_pdf[(NB + 1) * DIM];
    __shared__ float s_F[NB * DIM];

    const int t = threadIdx.x;

    if (t <= NB) {
        int e = t - 32;
        int a = e < 0 ? -e : e;
        double r1 = 1.2, r2 = r1 * r1, r4 = r2 * r2, r8 = r4 * r4,
               r16 = r8 * r8, r32 = r16 * r16;
        double pw = 1.0;
        if (a & 1)  pw *= r1;
        if (a & 2)  pw *= r2;
        if (a & 4)  pw *= r4;
        if (a & 8)  pw *= r8;
        if (a & 16) pw *= r16;
        double x1L = 10.0 * 0.2 / (r32 - 1.0);
        double xr  = x1L * (pw - 1.0) / 0.2;
        if (e < 0) xr = -xr;
        xr = (xr + 10.0) / 20.0;
        float mv = (float)xr;
        if (t == 0)  mv = 0.0f;
        if (t == NB) mv = 1.0f;
        s_mesh[t] = mv;
    }
    __syncthreads();
    if (t < NB) s_elmt[t] = s_mesh[t + 1] - s_mesh[t];
    for (int i = t; i < (NB - 1) * DIM; i += blockDim.x)
        s_ep[i] = expf(p[i]);
    __syncthreads();

    if (t < DIM) {
        float sum = 0.0f;
        for (int i = 0; i < NB - 1; i++)
            sum += s_ep[i * DIM + t] * 0.5f * (s_elmt[i] + s_elmt[i + 1]);
        float scale = (1.0f - (s_elmt[0] + s_elmt[NB - 1]) * BETA_F * 0.5f) / sum;

        s_pdf[t] = BETA_F;
        s_pdf[NB * DIM + t] = BETA_F;
        for (int i = 0; i < NB - 1; i++)
            s_pdf[(i + 1) * DIM + t] = scale * s_ep[i * DIM + t];

        s_F[t] = 0.0f;
        float cum = 0.0f;
        for (int i = 0; i < NB - 1; i++) {
            cum += 0.5f * (s_pdf[i * DIM + t] + s_pdf[(i + 1) * DIM + t]) * s_elmt[i];
            s_F[(i + 1) * DIM + t] = cum;
        }
    }
    __syncthreads();

    for (int i = t; i < NB * DIM; i += blockDim.x) {
        int k = i / DIM, d = i % DIM;
        float v1 = s_pdf[k * DIM + d];
        float v2 = s_pdf[(k + 1) * DIM + d];
        float h  = s_elmt[k];
        g_tab[d * NB + k] = make_float4(v1, (v2 - v1) / h,
                                        s_F[k * DIM + d], s_mesh[k]);
    }
}

// ---------------------------------------------------------------------------
// Main: one point/thread. Analytic bin index (1 MUFU), one LDS.128 per dim,
// grouped log-products (2 MUFU total for the 8-dim log sum).
// ---------------------------------------------------------------------------
__global__ void __launch_bounds__(256)
cdf_kernel(const float*  __restrict__ x,
           const float*  __restrict__ logdet_in,
           float*        __restrict__ y_out,
           float*        __restrict__ ld_out)
{
    __shared__ float4 s_tab[DIM * NB];

    const int t = threadIdx.x;
    s_tab[t]       = g_tab[t];
    s_tab[t + 256] = g_tab[t + 256];
    __syncthreads();

    const int i = blockIdx.x * 256 + t;

    const float4* xv = (const float4*)(x + (size_t)i * DIM);
    float4 a4 = xv[0], b4 = xv[1];
    float xr[DIM] = {a4.x, a4.y, a4.z, a4.w, b4.x, b4.y, b4.z, b4.w};
    float yv[DIM];
    float lsum = 0.0f;
    float prod0 = 1.0f, prod1 = 1.0f;

#pragma unroll
    for (int d = 0; d < DIM; d++) {
        float xi = xr[d];
        float xs = fmaf(xi, 0.05f, 0.5f);

        // analytic geometric bin index
        float tg = fmaf(fabsf(xi), GEO_C1, 1.0f);
        int   j  = (int)(__log2f(tg) * GEO_INVL);
        j = min(j, 31);
        int k = (xi >= 0.0f) ? (32 + j) : (31 - j);

        float4 tb = s_tab[d * NB + k];      // {v1, slope, F_pre, mesh_k}
        float  xm = xs - tb.w;

        float dld = fmaf(xm, tb.y, tb.x);
        float yq  = fmaf(xm, fmaf(0.5f * xm, tb.y, tb.x), tb.z);

        bool cover = (xs >= 0.0f) && (xs < 1.0f);
        if (!cover) { yq = xs; dld = 1.0f; }
        if (d < 4) prod0 *= dld; else prod1 *= dld;

        float yy = fmaf(yq, 20.0f, -10.0f);
        if (yy > 10.0f)  { lsum += LOG_BETA; yy = fmaf(BETA_F, yy - 10.0f,  10.0f); }
        if (yy < -10.0f) { lsum += LOG_BETA; yy = fmaf(BETA_F, yy + 10.0f, -10.0f); }
        yv[d] = yy;
    }

    lsum += __logf(prod0) + __logf(prod1);

    float4* yo = (float4*)(y_out + (size_t)i * DIM);
    yo[0] = make_float4(yv[0], yv[1], yv[2], yv[3]);
    yo[1] = make_float4(yv[4], yv[5], yv[6], yv[7]);
    ld_out[i] = logdet_in[i] + lsum;
}

extern "C" void kernel_launch(void* const* d_in, const int* in_sizes, int n_in,
                              void* d_out, int out_size)
{
    const float* x      = (const float*)d_in[0];
    const float* logdet = (const float*)d_in[1];
    const float* p      = (const float*)d_in[2];
    float* out    = (float*)d_out;
    float* y_out  = out;                        // [N*8]
    float* ld_out = out + (size_t)NPTS * DIM;   // [N]

    setup_kernel<<<1, 128>>>(p);
    cdf_kernel<<<NPTS / 256, 256>>>(x, logdet, y_out, ld_out);
}

// round 4
// speedup vs baseline: 2.3526x; 1.1568x over previous
#include <cuda_runtime.h>
#include <math.h>

#define NB     64
#define DIM    8
#define NPTS   2097152
#define BETA_F 1e-6f
#define LOG_BETA (-13.815511f)

// Geometric-mesh inversion: tg = |x|*(R^32-1)/10 + 1, j = floor(log2(tg)/log2(1.2))
#define GEO_C1   34.0821892f     // (1.2^32 - 1) / 10
#define GEO_INVL 3.80178402f     // 1 / log2(1.2)

// Per-(dim,bin) quadratic coefficients about u = xs-0.5, rebuilt each launch:
//   y(u)   = q0 + u*(q1 + u*q2)
//   dld(u) = q1 + 2*u*q2
__device__ float g_q0[DIM * NB];
__device__ float g_q1[DIM * NB];
__device__ float g_q2[DIM * NB];

// ---------------------------------------------------------------------------
// Setup: 8 warps, one per dim. Mesh via binary-expansion double powers,
// normalization via warp reduce, cumulative F via shfl scan (2 bins/lane),
// coefficients derived in double from the f32 reference quantities.
// ---------------------------------------------------------------------------
__global__ void setup_kernel(const float* __restrict__ p)
{
    __shared__ float s_mesh[NB + 1];
    __shared__ float s_elmt[NB];
    __shared__ float s_pdf[DIM][NB + 1];

    const int t = threadIdx.x;

    if (t <= NB) {
        int e = t - 32;
        int a = e < 0 ? -e : e;
        double r1 = 1.2, r2 = r1 * r1, r4 = r2 * r2, r8 = r4 * r4,
               r16 = r8 * r8, r32 = r16 * r16;
        double pw = 1.0;
        if (a & 1)  pw *= r1;
        if (a & 2)  pw *= r2;
        if (a & 4)  pw *= r4;
        if (a & 8)  pw *= r8;
        if (a & 16) pw *= r16;
        double xr = (2.0 / (r32 - 1.0)) * (pw - 1.0) / 0.2;
        if (e < 0) xr = -xr;
        xr = (xr + 10.0) / 20.0;
        float mv = (float)xr;
        if (t == 0)  mv = 0.0f;
        if (t == NB) mv = 1.0f;
        s_mesh[t] = mv;
    }
    __syncthreads();
    if (t < NB) s_elmt[t] = s_mesh[t + 1] - s_mesh[t];
    __syncthreads();

    const int d = t >> 5;      // warp = dim
    const int l = t & 31;      // lane

    // exp(p) for interior nodes; lane l handles indices l and l+32 (of 0..62)
    float ep_a = expf(p[l * DIM + d]);                            // i = l   (<=31)
    float ep_b = (l < 31) ? expf(p[(l + 32) * DIM + d]) : 0.0f;   // i = l+32 (<63)

    float wa = 0.5f * (s_elmt[l] + s_elmt[l + 1]);
    float wb = (l < 31) ? 0.5f * (s_elmt[l + 32] + s_elmt[l + 33]) : 0.0f;
    float sum = ep_a * wa + ep_b * wb;
#pragma unroll
    for (int o = 16; o; o >>= 1) sum += __shfl_xor_sync(0xFFFFFFFFu, sum, o);
    float scale = (1.0f - (s_elmt[0] + s_elmt[NB - 1]) * BETA_F * 0.5f) / sum;

    if (l == 0) { s_pdf[d][0] = BETA_F; s_pdf[d][NB] = BETA_F; }
    s_pdf[d][l + 1] = scale * ep_a;                // nodes 1..32
    if (l < 31) s_pdf[d][l + 33] = scale * ep_b;   // nodes 33..63
    __syncwarp();

    // cell integrals, bins k = l and k = l+32
    float ca = 0.5f * (s_pdf[d][l]      + s_pdf[d][l + 1])  * s_elmt[l];
    float cb = 0.5f * (s_pdf[d][l + 32] + s_pdf[d][l + 33]) * s_elmt[l + 32];

    // inclusive scans over lanes
    float A = ca, B = cb;
#pragma unroll
    for (int o = 1; o < 32; o <<= 1) {
        float va = __shfl_up_sync(0xFFFFFFFFu, A, o);
        float vb = __shfl_up_sync(0xFFFFFFFFu, B, o);
        if (l >= o) { A += va; B += vb; }
    }
    float A31 = __shfl_sync(0xFFFFFFFFu, A, 31);
    float Fa = A - ca;          // exclusive prefix at k = l
    float Fb = A31 + B - cb;    // exclusive prefix at k = l+32

#pragma unroll
    for (int half = 0; half < 2; half++) {
        int k = l + half * 32;
        double v1    = (double)s_pdf[d][k];
        double v2    = (double)s_pdf[d][k + 1];
        double h     = (double)s_elmt[k];                // f32 elmt, as reference
        double slope = (v2 - v1) / h;
        double mks   = (double)s_mesh[k] - 0.5;          // f32 mesh, as reference
        double F     = (double)(half ? Fb : Fa);
        double q1    = v1 - mks * slope;
        double q0    = F - mks * v1 + 0.5 * mks * mks * slope;
        int ti = d * NB + k;
        g_q0[ti] = (float)q0;
        g_q1[ti] = (float)q1;
        g_q2[ti] = (float)(0.5 * slope);
    }
}

// ---------------------------------------------------------------------------
// Main: one point/thread. Analytic bin index (1 MUFU/dim), 3x LDS.32 per dim
// (bank = k mod 32, conflict-light), grouped log-products (2 MUFU total).
// ---------------------------------------------------------------------------
__global__ void __launch_bounds__(256)
cdf_kernel(const float*  __restrict__ x,
           const float*  __restrict__ logdet_in,
           float*        __restrict__ y_out,
           float*        __restrict__ ld_out)
{
    __shared__ float s_q0[DIM * NB];
    __shared__ float s_q1[DIM * NB];
    __shared__ float s_q2[DIM * NB];

    const int t = threadIdx.x;
    s_q0[t] = g_q0[t]; s_q0[t + 256] = g_q0[t + 256];
    s_q1[t] = g_q1[t]; s_q1[t + 256] = g_q1[t + 256];
    s_q2[t] = g_q2[t]; s_q2[t + 256] = g_q2[t + 256];
    __syncthreads();

    const int i = blockIdx.x * 256 + t;

    const float4* xv = (const float4*)(x + (size_t)i * DIM);
    float4 a4 = xv[0], b4 = xv[1];
    float xr[DIM] = {a4.x, a4.y, a4.z, a4.w, b4.x, b4.y, b4.z, b4.w};
    float yv[DIM];
    float lsum = 0.0f;
    float prod0 = 1.0f, prod1 = 1.0f;

#pragma unroll
    for (int d = 0; d < DIM; d++) {
        float xi = xr[d];
        float xs = fmaf(xi, 0.05f, 0.5f);
        float u  = xs - 0.5f;

        // analytic geometric bin index
        float tg = fmaf(fabsf(xi), GEO_C1, 1.0f);
        int   j  = (int)(__log2f(tg) * GEO_INVL);
        j = min(j, 31);
        int k = (xi >= 0.0f) ? (32 + j) : (31 - j);

        int   ti = d * NB + k;
        float q0 = s_q0[ti], q1 = s_q1[ti], q2 = s_q2[ti];

        float tt  = u * q2;
        float dld = q1 + (tt + tt);
        float yq  = fmaf(u, q1 + tt, q0);

        bool cover = (xs >= 0.0f) && (xs < 1.0f);
        if (!cover) { yq = xs; dld = 1.0f; }
        if (d < 4) prod0 *= dld; else prod1 *= dld;

        float yy = fmaf(yq, 20.0f, -10.0f);
        if (yy > 10.0f)  { lsum += LOG_BETA; yy = fmaf(BETA_F, yy - 10.0f,  10.0f); }
        if (yy < -10.0f) { lsum += LOG_BETA; yy = fmaf(BETA_F, yy + 10.0f, -10.0f); }
        yv[d] = yy;
    }

    lsum += __logf(prod0) + __logf(prod1);

    float4* yo = (float4*)(y_out + (size_t)i * DIM);
    yo[0] = make_float4(yv[0], yv[1], yv[2], yv[3]);
    yo[1] = make_float4(yv[4], yv[5], yv[6], yv[7]);
    ld_out[i] = logdet_in[i] + lsum;
}

extern "C" void kernel_launch(void* const* d_in, const int* in_sizes, int n_in,
                              void* d_out, int out_size)
{
    const float* x      = (const float*)d_in[0];
    const float* logdet = (const float*)d_in[1];
    const float* p      = (const float*)d_in[2];
    float* out    = (float*)d_out;
    float* y_out  = out;                        // [N*8]
    float* ld_out = out + (size_t)NPTS * DIM;   // [N]

    setup_kernel<<<1, 256>>>(p);
    cdf_kernel<<<NPTS / 256, 256>>>(x, logdet, y_out, ld_out);
}

// round 5
// speedup vs baseline: 2.3757x; 1.0098x over previous
#include <cuda_runtime.h>
#include <math.h>

#define NB     64
#define DIM    8
#define NPTS   2097152
#define BETA_F 1e-6f
#define LOG_BETA (-13.815511f)

// Geometric-mesh inversion: tg = |x|*(R^32-1)/10 + 1, j = floor(log2(tg)/log2(1.2))
#define GEO_C1   34.0821892f     // (1.2^32 - 1) / 10
#define GEO_INVL 3.80178402f     // 1 / log2(1.2)

// Per-(dim,slot) quadratic coefficients about u = xs-0.5, rebuilt each launch:
//   y(u) = q0 + u*(q1 + u*q2),  dld(u) = q1 + 2u*q2
// Slot mapping (probability-aware bank pairing):
//   pos bin j  -> slot j              (bank j)
//   neg bin j  -> slot 32+((j+16)&31) (bank (j+16)%32)
__device__ float g_q0[DIM * NB];
__device__ float g_q1[DIM * NB];
__device__ float g_q2[DIM * NB];

// ---------------------------------------------------------------------------
// Setup: 8 warps, one per dim. Mesh via binary-expansion double powers,
// normalization via warp reduce, cumulative F via shfl scan (2 bins/lane).
// ---------------------------------------------------------------------------
__global__ void setup_kernel(const float* __restrict__ p)
{
    __shared__ float s_mesh[NB + 1];
    __shared__ float s_elmt[NB];
    __shared__ float s_pdf[DIM][NB + 1];

    const int t = threadIdx.x;

    if (t <= NB) {
        int e = t - 32;
        int a = e < 0 ? -e : e;
        double r1 = 1.2, r2 = r1 * r1, r4 = r2 * r2, r8 = r4 * r4,
               r16 = r8 * r8, r32 = r16 * r16;
        double pw = 1.0;
        if (a & 1)  pw *= r1;
        if (a & 2)  pw *= r2;
        if (a & 4)  pw *= r4;
        if (a & 8)  pw *= r8;
        if (a & 16) pw *= r16;
        double xr = (2.0 / (r32 - 1.0)) * (pw - 1.0) / 0.2;
        if (e < 0) xr = -xr;
        xr = (xr + 10.0) / 20.0;
        float mv = (float)xr;
        if (t == 0)  mv = 0.0f;
        if (t == NB) mv = 1.0f;
        s_mesh[t] = mv;
    }
    __syncthreads();
    if (t < NB) s_elmt[t] = s_mesh[t + 1] - s_mesh[t];
    __syncthreads();

    const int d = t >> 5;      // warp = dim
    const int l = t & 31;      // lane

    float ep_a = expf(p[l * DIM + d]);
    float ep_b = (l < 31) ? expf(p[(l + 32) * DIM + d]) : 0.0f;

    float wa = 0.5f * (s_elmt[l] + s_elmt[l + 1]);
    float wb = (l < 31) ? 0.5f * (s_elmt[l + 32] + s_elmt[l + 33]) : 0.0f;
    float sum = ep_a * wa + ep_b * wb;
#pragma unroll
    for (int o = 16; o; o >>= 1) sum += __shfl_xor_sync(0xFFFFFFFFu, sum, o);
    float scale = (1.0f - (s_elmt[0] + s_elmt[NB - 1]) * BETA_F * 0.5f) / sum;

    if (l == 0) { s_pdf[d][0] = BETA_F; s_pdf[d][NB] = BETA_F; }
    s_pdf[d][l + 1] = scale * ep_a;
    if (l < 31) s_pdf[d][l + 33] = scale * ep_b;
    __syncwarp();

    float ca = 0.5f * (s_pdf[d][l]      + s_pdf[d][l + 1])  * s_elmt[l];
    float cb = 0.5f * (s_pdf[d][l + 32] + s_pdf[d][l + 33]) * s_elmt[l + 32];

    float A = ca, B = cb;
#pragma unroll
    for (int o = 1; o < 32; o <<= 1) {
        float va = __shfl_up_sync(0xFFFFFFFFu, A, o);
        float vb = __shfl_up_sync(0xFFFFFFFFu, B, o);
        if (l >= o) { A += va; B += vb; }
    }
    float A31 = __shfl_sync(0xFFFFFFFFu, A, 31);
    float Fa = A - ca;
    float Fb = A31 + B - cb;

#pragma unroll
    for (int half = 0; half < 2; half++) {
        int k = l + half * 32;
        double v1    = (double)s_pdf[d][k];
        double v2    = (double)s_pdf[d][k + 1];
        double h     = (double)s_elmt[k];
        double slope = (v2 - v1) / h;
        double mks   = (double)s_mesh[k] - 0.5;
        double F     = (double)(half ? Fb : Fa);
        double q1    = v1 - mks * slope;
        double q0    = F - mks * v1 + 0.5 * mks * mks * slope;
        // slot mapping: k>=32 (pos bin j=k-32) -> j ; k<32 (neg bin j=31-k) -> 32+((j+16)&31)
        int s = (k >= 32) ? (k - 32) : (32 + ((47 - k) & 31));
        int ti = d * NB + s;
        g_q0[ti] = (float)q0;
        g_q1[ti] = (float)q1;
        g_q2[ti] = (float)(0.5 * slope);
    }
}

// ---------------------------------------------------------------------------
// Main: one point/thread. x LDG hoisted above staging; bank-paired table.
// ---------------------------------------------------------------------------
__global__ void __launch_bounds__(256)
cdf_kernel(const float*  __restrict__ x,
           const float*  __restrict__ logdet_in,
           float*        __restrict__ y_out,
           float*        __restrict__ ld_out)
{
    __shared__ float s_q0[DIM * NB];
    __shared__ float s_q1[DIM * NB];
    __shared__ float s_q2[DIM * NB];

    const int t = threadIdx.x;
    const int i = blockIdx.x * 256 + t;

    // issue point loads first — overlap DRAM latency with table staging
    const float4* xv = (const float4*)(x + (size_t)i * DIM);
    float4 a4 = xv[0], b4 = xv[1];
    float ld_in = logdet_in[i];

    if (t < 128) {
        ((float4*)s_q0)[t] = ((const float4*)g_q0)[t];
        ((float4*)s_q1)[t] = ((const float4*)g_q1)[t];
        ((float4*)s_q2)[t] = ((const float4*)g_q2)[t];
    }
    __syncthreads();

    float xr[DIM] = {a4.x, a4.y, a4.z, a4.w, b4.x, b4.y, b4.z, b4.w};
    float yv[DIM];
    float lsum = 0.0f;
    float prod0 = 1.0f, prod1 = 1.0f;

#pragma unroll
    for (int d = 0; d < DIM; d++) {
        float xi = xr[d];
        float u  = xi * 0.05f;

        // analytic geometric bin index
        float tg = fmaf(fabsf(xi), GEO_C1, 1.0f);
        int   j  = (int)(__log2f(tg) * GEO_INVL);
        j = min(j, 31);
        int s = (xi < 0.0f) ? (32 + ((j + 16) & 31)) : j;

        int   ti = d * NB + s;
        float q0 = s_q0[ti], q1 = s_q1[ti], q2 = s_q2[ti];

        float u2  = u + u;
        float dld = fmaf(u2, q2, q1);
        float yq  = fmaf(u, fmaf(u, q2, q1), q0);

        bool cover = (xi >= -10.0f) && (xi < 10.0f);
        float yy = cover ? fmaf(yq, 20.0f, -10.0f) : xi;
        float dd = cover ? dld : 1.0f;
        if (d < 4) prod0 *= dd; else prod1 *= dd;

        if (yy > 10.0f)  { lsum += LOG_BETA; yy = fmaf(BETA_F, yy - 10.0f,  10.0f); }
        if (yy < -10.0f) { lsum += LOG_BETA; yy = fmaf(BETA_F, yy + 10.0f, -10.0f); }
        yv[d] = yy;
    }

    lsum += __logf(prod0) + __logf(prod1);

    float4* yo = (float4*)(y_out + (size_t)i * DIM);
    yo[0] = make_float4(yv[0], yv[1], yv[2], yv[3]);
    yo[1] = make_float4(yv[4], yv[5], yv[6], yv[7]);
    ld_out[i] = ld_in + lsum;
}

extern "C" void kernel_launch(void* const* d_in, const int* in_sizes, int n_in,
                              void* d_out, int out_size)
{
    const float* x      = (const float*)d_in[0];
    const float* logdet = (const float*)d_in[1];
    const float* p      = (const float*)d_in[2];
    float* out    = (float*)d_out;
    float* y_out  = out;                        // [N*8]
    float* ld_out = out + (size_t)NPTS * DIM;   // [N]

    setup_kernel<<<1, 256>>>(p);
    cdf_kernel<<<NPTS / 256, 256>>>(x, logdet, y_out, ld_out);
}